// round 4
// baseline (speedup 1.0000x reference)
#include <cuda_runtime.h>
#include <cuda_bf16.h>

// 6-level cascaded db4 DWT, zero-padding mode, fully fused in one kernel.
//
// Per level: out[i] = sum_{m=0..7} x[2i-6+m] * REV[m]   (REV = reversed filter),
// zero outside [0, N). M = (N+7)/2.
//
// Tiling: each block owns T=64 level-6 outputs. To produce them it computes all
// levels over left-haloed ranges: h6=0, h_{l-1}=2*h_l+6 -> h1=186, input halo 378.
// Buffer base at level l: base_l = c*T*2^(6-l) - h_l, so base_{l-1} = 2*base_l - 6
// and the conv input for local index j is exactly sin[2j+m]. Out-of-range global
// indices store 0 (zero-pad semantics, both edges). Each detail element is written
// by exactly one block (the one with j >= h_l).

#define TPB 256
#define TT  64   // level-6 outputs per block

__device__ __constant__ float RLO[8] = {
     0.23037781330885523f,  0.7148465705525415f,   0.6308807679295904f,
    -0.02798376941698385f, -0.18703481171888114f,  0.030841381835986965f,
     0.032883011666982945f, -0.010597401784997278f };
__device__ __constant__ float RHI[8] = {
    -0.010597401784997278f, -0.032883011666982945f, 0.030841381835986965f,
     0.18703481171888114f,  -0.02798376941698385f, -0.6308807679295904f,
     0.7148465705525415f,   -0.23037781330885523f };

// Output element-offset layout (row-major [64, M] each), order:
//   a(4102), d6(4102), d5(8198), d4(16390), d3(32774), d2(65541), d1(131075)
//   a:0  d6:262528  d5:525056  d4:1049728  d3:2098688  d2:4196224  d1:8390848

template<int P, int LEN, int H, int DBASE, bool LAST>
__device__ __forceinline__ void level_step(const float* __restrict__ sin,
                                           float* __restrict__ sout,
                                           float* __restrict__ out,
                                           int c, int r, int tid) {
    const int S    = TT * P + H;           // compute-range size at this level
    const int base = c * (TT * P) - H;     // global index of sin/sout local 0
    float* __restrict__ dr = out + (size_t)DBASE + (size_t)r * LEN;
    for (int j = tid; j < S; j += TPB) {
        const int g = base + j;
        float lo = 0.f, hi = 0.f;
        if ((unsigned)g < (unsigned)LEN) {
            #pragma unroll
            for (int m = 0; m < 8; m++) {
                const float v = sin[2 * j + m];
                lo = fmaf(v, RLO[m], lo);
                hi = fmaf(v, RHI[m], hi);
            }
        }
        if (!LAST) sout[j] = lo;                       // 0 outside [0,LEN): zero-pad for next level
        if (j >= H && (unsigned)g < (unsigned)LEN) {   // owned & in-range -> unique writer
            dr[g] = hi;                                // detail coeff
            if (LAST) out[(size_t)r * LEN + g] = lo;   // final approximation (cA6)
        }
    }
}

__global__ void __launch_bounds__(TPB)
dwt6_fused_kernel(const float* __restrict__ x, float* __restrict__ out) {
    __shared__ float s0[64 * TT + 378];  // 4474
    __shared__ float s1[32 * TT + 186];  // 2234
    __shared__ float s2[16 * TT + 90];   // 1114
    __shared__ float s3[ 8 * TT + 42];   //  554
    __shared__ float s4[ 4 * TT + 18];   //  274
    __shared__ float s5[ 2 * TT + 6];    //  134

    const int c   = blockIdx.x;
    const int r   = blockIdx.y;
    const int tid = threadIdx.x;

    const float* __restrict__ xr = x + (size_t)r * 262144;
    const int base0 = c * (TT * 64) - 378;

    // Load input tile + halo, zero-padded.
    #pragma unroll 4
    for (int j = tid; j < 64 * TT + 378; j += TPB) {
        const int g = base0 + j;
        s0[j] = ((unsigned)g < 262144u) ? __ldg(xr + g) : 0.f;
    }
    __syncthreads();

    level_step<32, 131075, 186, 8390848, false>(s0, s1, out, c, r, tid);  // d1
    __syncthreads();
    level_step<16,  65541,  90, 4196224, false>(s1, s2, out, c, r, tid);  // d2
    __syncthreads();
    level_step< 8,  32774,  42, 2098688, false>(s2, s3, out, c, r, tid);  // d3
    __syncthreads();
    level_step< 4,  16390,  18, 1049728, false>(s3, s4, out, c, r, tid);  // d4
    __syncthreads();
    level_step< 2,   8198,   6,  525056, false>(s4, s5, out, c, r, tid);  // d5
    __syncthreads();
    level_step< 1,   4102,   0,  262528, true >(s5, (float*)0, out, c, r, tid);  // d6 + a
}

extern "C" void kernel_launch(void* const* d_in, const int* in_sizes, int n_in,
                              void* d_out, int out_size) {
    const float* x = (const float*)d_in[0];
    float* out = (float*)d_out;
    const int rows = in_sizes[0] / 262144;          // 64
    const int chunks = (4102 + TT - 1) / TT;        // 65
    dim3 grid(chunks, rows);
    dwt6_fused_kernel<<<grid, TPB>>>(x, out);
}